// round 7
// baseline (speedup 1.0000x reference)
#include <cuda_runtime.h>
#include <cstddef>
#include <cstdint>

#define THREADS   256
#define SXS       258     // X stride: 256+2 (even -> 8B LDS; 258%32==2 -> conflict-free A reads)
#define SWS       34      // W stride: 32+2
#define KCHUNK    32
#define NCH       8       // 256 / KCHUNK
#define B_TARGETS 4096
#define L1_ROWS   (B_TARGETS * 11)   // 45056

// Layer-1 hidden representations scratch (23 MB).
__device__ __align__(256) float g_h1[L1_ROWS * 128];

typedef unsigned long long u64;

__device__ __forceinline__ void ffma2(u64& d, u64 a, u64 b) {
    asm("fma.rn.f32x2 %0, %1, %2, %0;" : "+l"(d) : "l"(a), "l"(b));
}
__device__ __forceinline__ void add2(u64& d, u64 a) {
    asm("add.rn.f32x2 %0, %1, %0;" : "+l"(d) : "l"(a));
}
__device__ __forceinline__ u64 pack2(float lo, float hi) {
    u64 r; asm("mov.b64 %0, {%1, %2};" : "=l"(r) : "f"(lo), "f"(hi)); return r;
}
__device__ __forceinline__ float2 unpack2(u64 v) {
    float2 r; asm("mov.b64 {%0, %1}, %2;" : "=f"(r.x), "=f"(r.y) : "l"(v)); return r;
}
__device__ __forceinline__ u64 mul2(u64 a, u64 b) {
    u64 r; asm("mul.rn.f32x2 %0, %1, %2;" : "=l"(r) : "l"(a), "l"(b)); return r;
}
__device__ __forceinline__ void cpa8(uint32_t dst, const float* src) {
    asm volatile("cp.async.ca.shared.global [%0], [%1], 8;" :: "r"(dst), "l"(src));
}
__device__ __forceinline__ void cpa_commit() {
    asm volatile("cp.async.commit_group;");
}
__device__ __forceinline__ void cpa_wait_all() {
    asm volatile("cp.async.wait_group 0;");
}

// Fused per tile: gather+mean -> sX [BM x 256], then
// Y = l2norm_rows(relu(sX @ W^T + bias)) -> out [BM x 128].
// 256 threads = NT col-groups (NJ cols each) x MT row-groups (MI rows each,
// rows interleaved: m = mt + MT*mi). W staged in 8 K-chunks of 32, cp.async
// double-buffered. LAYER 0: rows = level-1 nodes. LAYER 1: rows = targets.
template <int LAYER, int BM, int NJ>
__global__ __launch_bounds__(THREADS, 3)
void sage_layer(const float* __restrict__ src,
                const int*   __restrict__ nodes,
                const int*   __restrict__ nbr1,
                const int*   __restrict__ nbr0,
                const float* __restrict__ W,      // [128][256] row-major
                const float* __restrict__ bias,   // [128]
                float*       __restrict__ out)    // [rows][128]
{
    constexpr int NT = 128 / NJ;       // col groups
    constexpr int MT = THREADS / NT;   // row groups
    constexpr int MI = BM / MT;        // rows per thread

    extern __shared__ float smem[];
    float* sX    = smem;                     // BM * SXS
    float* sW    = sX + BM * SXS;            // 2 * 128 * SWS (double buffer)
    float* sBias = sW + 2 * 128 * SWS;       // 128
    float* sPart = sBias + 128;              // NT * BM
    float* sInv  = sPart + NT * BM;          // BM

    const int tid  = threadIdx.x;
    const int warp = tid >> 5;
    const int lane = tid & 31;
    const int m0   = blockIdx.x * BM;

    const uint32_t sWu = static_cast<uint32_t>(__cvta_generic_to_shared(sW));

    auto load_chunk = [&](int kc, int b) {
        const float* wsrc = W + kc * KCHUNK;
        const uint32_t dst = sWu + (uint32_t)b * (128 * SWS * 4);
        #pragma unroll
        for (int t = 0; t < (128 * KCHUNK / 2) / THREADS; ++t) {   // 8
            const int e  = tid + t * THREADS;   // 0..2047
            const int h  = e >> 4;              // 0..127
            const int c2 = e & 15;              // 8B pair within 32 cols
            cpa8(dst + (uint32_t)(h * SWS + c2 * 2) * 4,
                 wsrc + h * 256 + c2 * 2);
        }
        cpa_commit();
    };

    load_chunk(0, 0);                    // latency hidden under the gather

    if (tid < 128) sBias[tid] = bias[tid];

    // ---------------- gather: warp w builds rows w*RPW .. ------------------
    constexpr int RPW = BM / 8;
    #pragma unroll
    for (int r = 0; r < RPW; ++r) {
        const int mL = warp * RPW + r;
        float4 self;
        u64 a01a = 0, a23a = 0, a01b = 0, a23b = 0;   // two f32x2 chains
        u64 scale;

        if (LAYER == 0) {
            const int j   = m0 + mL;            // level-1 node id
            const int b   = j / 11;
            const int col = j - b * 11;
            const int sidx = (col == 0) ? __ldg(&nodes[b])
                                        : __ldg(&nbr1[b * 10 + col - 1]);
            self = ((const float4*)(src + (size_t)sidx * 128))[lane];

            const int* nb = nbr0 + (size_t)j * 25;
            int myidx = (lane < 25) ? __ldg(&nb[lane]) : 0;
            #pragma unroll
            for (int s = 0; s < 25; ++s) {
                const int ni = __shfl_sync(0xffffffffu, myidx, s);
                float4 v = ((const float4*)(src + (size_t)ni * 128))[lane];
                if (s & 1) { add2(a01b, pack2(v.x, v.y)); add2(a23b, pack2(v.z, v.w)); }
                else       { add2(a01a, pack2(v.x, v.y)); add2(a23a, pack2(v.z, v.w)); }
            }
            scale = pack2(1.0f / 25.0f, 1.0f / 25.0f);
        } else {
            const int b = m0 + mL;              // target index
            const float* base = src + (size_t)b * (11 * 128);
            self = ((const float4*)base)[lane];
            #pragma unroll
            for (int s = 1; s <= 10; ++s) {
                float4 v = ((const float4*)(base + s * 128))[lane];
                if (s & 1) { add2(a01b, pack2(v.x, v.y)); add2(a23b, pack2(v.z, v.w)); }
                else       { add2(a01a, pack2(v.x, v.y)); add2(a23a, pack2(v.z, v.w)); }
            }
            scale = pack2(0.1f, 0.1f);
        }

        add2(a01a, a01b);
        add2(a23a, a23b);
        const float2 m01 = unpack2(mul2(a01a, scale));
        const float2 m23 = unpack2(mul2(a23a, scale));

        float* dst = sX + mL * SXS;             // row base 8B-aligned (258 even)
        ((float2*)dst)[2 * lane + 0]         = make_float2(self.x, self.y);
        ((float2*)dst)[2 * lane + 1]         = make_float2(self.z, self.w);
        ((float2*)(dst + 128))[2 * lane + 0] = m01;
        ((float2*)(dst + 128))[2 * lane + 1] = m23;
    }

    // ---------------- GEMM, packed f32x2, pipelined W chunks ---------------
    const int nt = tid / MT;     // col group: cols nt*NJ .. +NJ-1
    const int mt = tid % MT;     // row group: rows mt, mt+MT, ...

    u64 acc2[MI][NJ];
    #pragma unroll
    for (int mi = 0; mi < MI; ++mi)
        #pragma unroll
        for (int j = 0; j < NJ; ++j) acc2[mi][j] = 0ull;

    #pragma unroll 1
    for (int kc = 0; kc < NCH; ++kc) {
        cpa_wait_all();          // chunk kc landed (this thread's part)
        __syncthreads();         // publish cp.async + (kc==0) gather; fences
                                 // buffer about to be overwritten
        if (kc < NCH - 1) load_chunk(kc + 1, (kc + 1) & 1);

        const float* bp = sW + (size_t)(kc & 1) * (128 * SWS) + (nt * NJ) * SWS;
        const float* ap = sX + mt * SXS + kc * KCHUNK;

        #pragma unroll 4
        for (int kk2 = 0; kk2 < KCHUNK / 2; ++kk2) {
            u64 bv[NJ];
            #pragma unroll
            for (int j = 0; j < NJ; ++j)
                bv[j] = *(const u64*)(bp + j * SWS + 2 * kk2);
            #pragma unroll
            for (int mi = 0; mi < MI; ++mi) {
                const u64 av = *(const u64*)(ap + mi * (MT * SXS) + 2 * kk2);
                #pragma unroll
                for (int j = 0; j < NJ; ++j) ffma2(acc2[mi][j], av, bv[j]);
            }
        }
    }

    // ---------------- epilogue: bias + relu + row L2 norm + store ----------
    float vals[MI][NJ];
    #pragma unroll
    for (int mi = 0; mi < MI; ++mi) {
        const int m = mt + MT * mi;
        float ss = 0.f;
        #pragma unroll
        for (int j = 0; j < NJ; ++j) {
            const float2 p = unpack2(acc2[mi][j]);
            const float v = fmaxf(p.x + p.y + sBias[nt * NJ + j], 0.f);
            vals[mi][j] = v;
            ss += v * v;
        }
        sPart[nt * BM + m] = ss;
    }
    __syncthreads();

    if (tid < BM) {
        float t = 0.f;
        #pragma unroll
        for (int n = 0; n < NT; ++n) t += sPart[n * BM + tid];
        sInv[tid] = 1.0f / fmaxf(sqrtf(t), 1e-12f);
    }
    __syncthreads();

    #pragma unroll
    for (int mi = 0; mi < MI; ++mi) {
        const int m = mt + MT * mi;
        const float inv = sInv[m];
        float* op = out + (size_t)(m0 + m) * 128 + nt * NJ;
        #pragma unroll
        for (int q = 0; q < NJ / 4; ++q)
            ((float4*)op)[q] = make_float4(vals[mi][4 * q + 0] * inv,
                                           vals[mi][4 * q + 1] * inv,
                                           vals[mi][4 * q + 2] * inv,
                                           vals[mi][4 * q + 3] * inv);
    }
}

extern "C" void kernel_launch(void* const* d_in, const int* in_sizes, int n_in,
                              void* d_out, int out_size)
{
    (void)in_sizes; (void)n_in; (void)out_size;

    const float* features = (const float*)d_in[0];
    const float* W0       = (const float*)d_in[1];
    const float* b0       = (const float*)d_in[2];
    const float* W1       = (const float*)d_in[3];
    const float* b1       = (const float*)d_in[4];
    const int*   nodes    = (const int*)d_in[5];
    const int*   nbr1     = (const int*)d_in[6];
    const int*   nbr0     = (const int*)d_in[7];
    float*       out      = (float*)d_out;

    // Layer 0: BM=32, NJ=8  -> NT=16, MT=16, MI=2. grid=1408, 3 blocks/SM.
    // Layer 1: BM=8,  NJ=4  -> NT=32, MT=8,  MI=1. grid=512.
    const int SMEM0 = (32 * SXS + 2 * 128 * SWS + 128 + 16 * 32 + 32)
                      * (int)sizeof(float);   // 70,528 B
    const int SMEM1 = (8 * SXS + 2 * 128 * SWS + 128 + 32 * 8 + 8)
                      * (int)sizeof(float);   // 44,640 B

    cudaFuncSetAttribute(sage_layer<0, 32, 8>,
                         cudaFuncAttributeMaxDynamicSharedMemorySize, SMEM0);
    cudaFuncSetAttribute(sage_layer<0, 32, 8>,
                         cudaFuncAttributePreferredSharedMemoryCarveout, 100);
    cudaFuncSetAttribute(sage_layer<1, 8, 4>,
                         cudaFuncAttributeMaxDynamicSharedMemorySize, SMEM1);
    cudaFuncSetAttribute(sage_layer<1, 8, 4>,
                         cudaFuncAttributePreferredSharedMemoryCarveout, 100);

    float* h1 = nullptr;
    cudaGetSymbolAddress((void**)&h1, g_h1);

    sage_layer<0, 32, 8><<<L1_ROWS / 32, THREADS, SMEM0>>>(
        features, nodes, nbr1, nbr0, W0, b0, h1);
    sage_layer<1, 8, 4><<<B_TARGETS / 8, THREADS, SMEM1>>>(
        h1, nullptr, nullptr, nullptr, W1, b1, out);
}

// round 9
// speedup vs baseline: 1.1994x; 1.1994x over previous
#include <cuda_runtime.h>
#include <cuda_bf16.h>
#include <cstdint>
#include <cstddef>

#define THREADS   256
#define BM        64
#define AS        264     // A row stride in bf16 (264*2B: rows shift 4 words mod 32 -> ldmatrix conflict-free)
#define BS        40      // B chunk row stride in bf16 (80B: rows shift 20 words mod 32 -> conflict-free)
#define B_TARGETS 4096
#define L1_ROWS   (B_TARGETS * 11)   // 45056

// Scratch: layer-1 hidden reps (fp32) + pre-split bf16 hi/lo weights.
__device__ __align__(256) float         g_h1[L1_ROWS * 128];
__device__ __align__(256) __nv_bfloat16 g_W0h[128 * 256];
__device__ __align__(256) __nv_bfloat16 g_W0l[128 * 256];
__device__ __align__(256) __nv_bfloat16 g_W1h[128 * 256];
__device__ __align__(256) __nv_bfloat16 g_W1l[128 * 256];

struct Smem {
    __nv_bfloat16 Ah[BM * AS];          // 33792 B
    __nv_bfloat16 Al[BM * AS];          // 33792 B
    __nv_bfloat16 Bt[2][2][128 * BS];   // [buf][hi/lo], 4*10240 B
    float bias[128];
    float red[4][BM];
    float inv[BM];
};                                       // 110336 B total

typedef unsigned long long u64;

// ---- scalar helpers ----
__device__ __forceinline__ float bfrt(float x) {            // fp32 -> bf16 -> fp32
    float r;
    asm("{\n\t.reg .b16 t;\n\tcvt.rn.bf16.f32 t, %1;\n\tcvt.f32.bf16 %0, t;\n\t}"
        : "=f"(r) : "f"(x));
    return r;
}
__device__ __forceinline__ uint32_t pk_bf16(float x, float y) {  // -> bf16x2 (lo=x)
    uint32_t r;
    asm("{\n\t.reg .b16 l, h;\n\tcvt.rn.bf16.f32 l, %1;\n\tcvt.rn.bf16.f32 h, %2;\n\t"
        "mov.b32 %0, {l, h};\n\t}" : "=r"(r) : "f"(x), "f"(y));
    return r;
}
// f32x2 gather accumulation
__device__ __forceinline__ void add2(u64& d, u64 a) {
    asm("add.rn.f32x2 %0, %1, %0;" : "+l"(d) : "l"(a));
}
__device__ __forceinline__ u64 pack2(float lo, float hi) {
    u64 r; asm("mov.b64 %0, {%1, %2};" : "=l"(r) : "f"(lo), "f"(hi)); return r;
}
__device__ __forceinline__ float2 unpack2(u64 v) {
    float2 r; asm("mov.b64 {%0, %1}, %2;" : "=f"(r.x), "=f"(r.y) : "l"(v)); return r;
}
__device__ __forceinline__ u64 mul2(u64 a, u64 b) {
    u64 r; asm("mul.rn.f32x2 %0, %1, %2;" : "=l"(r) : "l"(a), "l"(b)); return r;
}
// ---- async copy ----
__device__ __forceinline__ void cp16(uint32_t dst, const void* src) {
    asm volatile("cp.async.cg.shared.global [%0], [%1], 16;" :: "r"(dst), "l"(src));
}
__device__ __forceinline__ void cpa_commit() {
    asm volatile("cp.async.commit_group;");
}
template <int N>
__device__ __forceinline__ void cpa_wait() {
    asm volatile("cp.async.wait_group %0;" :: "n"(N));
}
// ---- tensor core (legacy HMMA path; valid on base sm_103 target) ----
__device__ __forceinline__ void ldsm4(uint32_t* r, uint32_t addr) {
    asm volatile("ldmatrix.sync.aligned.m8n8.x4.shared.b16 {%0,%1,%2,%3}, [%4];"
                 : "=r"(r[0]), "=r"(r[1]), "=r"(r[2]), "=r"(r[3]) : "r"(addr));
}
__device__ __forceinline__ void mma_bf16(float* c, const uint32_t* a,
                                         uint32_t b0, uint32_t b1) {
    asm volatile("mma.sync.aligned.m16n8k16.row.col.f32.bf16.bf16.f32 "
                 "{%0,%1,%2,%3}, {%4,%5,%6,%7}, {%8,%9}, {%0,%1,%2,%3};"
                 : "+f"(c[0]), "+f"(c[1]), "+f"(c[2]), "+f"(c[3])
                 : "r"(a[0]), "r"(a[1]), "r"(a[2]), "r"(a[3]), "r"(b0), "r"(b1));
}

// Pre-split W0/W1 into bf16 hi/lo (one-time, L2-resident afterwards).
__global__ void prep_w(const float* __restrict__ W0, const float* __restrict__ W1) {
    const int i = blockIdx.x * 256 + threadIdx.x;      // 0..32767
    const float a = W0[i], b = W1[i];
    g_W0h[i] = __float2bfloat16(a);
    g_W0l[i] = __float2bfloat16(a - bfrt(a));
    g_W1h[i] = __float2bfloat16(b);
    g_W1l[i] = __float2bfloat16(b - bfrt(b));
}

// Fused tile: gather+mean -> bf16 hi/lo A in smem -> HMMA (3-product bf16
// split, fp32 accum) -> bias+relu+row-l2norm -> out.
// Block: 64 rows, 256 threads = 8 warps: wm=warp&1 (M32), wn=warp>>1 (N32).
// LAYER 0: rows = level-1 nodes (self feat || mean of 25 nbr feats).
// LAYER 1: rows = targets       (h1[b,0]   || mean of h1[b,1..10]).
template <int LAYER>
__global__ __launch_bounds__(THREADS, 2)
void sage_hmma(const float* __restrict__ src,
               const int*   __restrict__ nodes,
               const int*   __restrict__ nbr1,
               const int*   __restrict__ nbr0,
               const __nv_bfloat16* __restrict__ Wh,   // [128 n][256 k]
               const __nv_bfloat16* __restrict__ Wl,
               const float* __restrict__ bias,
               float*       __restrict__ out)          // [rows][128]
{
    extern __shared__ char smraw[];
    Smem& S = *(Smem*)smraw;

    const int tid  = threadIdx.x;
    const int warp = tid >> 5;
    const int lane = tid & 31;
    const int m0   = blockIdx.x * BM;
    const int wm   = warp & 1;          // M group  (rows wm*32..+31)
    const int wn   = warp >> 1;         // N group  (cols wn*32..+31)
    const int Rb   = wm * 32;
    const int Nb   = wn * 32;

    const uint32_t uAh = (uint32_t)__cvta_generic_to_shared(S.Ah);
    const uint32_t uAl = (uint32_t)__cvta_generic_to_shared(S.Al);
    const uint32_t uBt = (uint32_t)__cvta_generic_to_shared(S.Bt);

    // Stage W chunk kc (32 k-cols, hi+lo) into buffer `buf` via cp.async.
    auto load_chunk = [&](int kc, int buf) {
        #pragma unroll
        for (int t = 0; t < 4; ++t) {
            const int e     = tid + t * THREADS;   // 0..1023
            const int piece = e & 3;               // 16B piece (8 bf16)
            const int n     = (e >> 2) & 127;
            const int hl    = e >> 9;              // 0=hi, 1=lo
            const __nv_bfloat16* sp = (hl ? Wl : Wh) + n * 256 + kc * 32 + piece * 8;
            const uint32_t dst = uBt + (uint32_t)(buf * 2 + hl) * (128 * BS * 2)
                                     + (uint32_t)(n * BS + piece * 8) * 2;
            cp16(dst, sp);
        }
        cpa_commit();
    };

    load_chunk(0, 0);
    load_chunk(1, 1);                    // both hide under the gather

    if (tid < 128) S.bias[tid] = bias[tid];

    // ---------------- gather: warp w builds rows w*8 .. w*8+7 --------------
    #pragma unroll 1
    for (int r = 0; r < 8; ++r) {
        const int mL = warp * 8 + r;
        float4 self;
        u64 a01a = 0, a23a = 0, a01b = 0, a23b = 0;
        u64 scale;

        if (LAYER == 0) {
            const int j   = m0 + mL;
            const int b   = j / 11;
            const int col = j - b * 11;
            const int sidx = (col == 0) ? __ldg(&nodes[b])
                                        : __ldg(&nbr1[b * 10 + col - 1]);
            self = ((const float4*)(src + (size_t)sidx * 128))[lane];
            const int* nb = nbr0 + (size_t)j * 25;
            int myidx = (lane < 25) ? __ldg(&nb[lane]) : 0;
            #pragma unroll
            for (int s = 0; s < 25; ++s) {
                const int ni = __shfl_sync(0xffffffffu, myidx, s);
                float4 v = ((const float4*)(src + (size_t)ni * 128))[lane];
                if (s & 1) { add2(a01b, pack2(v.x, v.y)); add2(a23b, pack2(v.z, v.w)); }
                else       { add2(a01a, pack2(v.x, v.y)); add2(a23a, pack2(v.z, v.w)); }
            }
            scale = pack2(1.0f / 25.0f, 1.0f / 25.0f);
        } else {
            const int b = m0 + mL;
            const float* base = src + (size_t)b * (11 * 128);
            self = ((const float4*)base)[lane];
            #pragma unroll
            for (int s = 1; s <= 10; ++s) {
                float4 v = ((const float4*)(base + s * 128))[lane];
                if (s & 1) { add2(a01b, pack2(v.x, v.y)); add2(a23b, pack2(v.z, v.w)); }
                else       { add2(a01a, pack2(v.x, v.y)); add2(a23a, pack2(v.z, v.w)); }
            }
            scale = pack2(0.1f, 0.1f);
        }
        add2(a01a, a01b);
        add2(a23a, a23b);
        const float2 m01 = unpack2(mul2(a01a, scale));
        const float2 m23 = unpack2(mul2(a23a, scale));

        // rows: self at cols 4*lane.., mean at cols 128+4*lane..
        __nv_bfloat16* rowH = S.Ah + mL * AS;
        __nv_bfloat16* rowL = S.Al + mL * AS;
        *(uint2*)(rowH + 4 * lane) =
            make_uint2(pk_bf16(self.x, self.y), pk_bf16(self.z, self.w));
        *(uint2*)(rowL + 4 * lane) =
            make_uint2(pk_bf16(self.x - bfrt(self.x), self.y - bfrt(self.y)),
                       pk_bf16(self.z - bfrt(self.z), self.w - bfrt(self.w)));
        *(uint2*)(rowH + 128 + 4 * lane) =
            make_uint2(pk_bf16(m01.x, m01.y), pk_bf16(m23.x, m23.y));
        *(uint2*)(rowL + 128 + 4 * lane) =
            make_uint2(pk_bf16(m01.x - bfrt(m01.x), m01.y - bfrt(m01.y)),
                       pk_bf16(m23.x - bfrt(m23.x), m23.y - bfrt(m23.y)));
    }

    // ---------------- HMMA mainloop over 8 K32 chunks ----------------------
    float acc[2][4][4];
    #pragma unroll
    for (int mt = 0; mt < 2; ++mt)
        #pragma unroll
        for (int nt = 0; nt < 4; ++nt)
            #pragma unroll
            for (int c = 0; c < 4; ++c) acc[mt][nt][c] = 0.f;

    const int li = lane >> 3;      // ldmatrix matrix index 0..3
    const int lr = lane & 7;       // row within matrix

    #pragma unroll 1
    for (int kc = 0; kc < 8; ++kc) {
        if (kc == 7) cpa_wait<0>(); else cpa_wait<1>();
        __syncthreads();           // publish chunk kc (+ gather A on kc==0)

        const uint32_t bufb = uBt + (uint32_t)((kc & 1) * 2) * (128 * BS * 2);

        #pragma unroll
        for (int s = 0; s < 2; ++s) {
            const int k0g  = kc * 32 + s * 16;
            const int kloc = s * 16;

            uint32_t Ahf[2][4], Alf[2][4];
            #pragma unroll
            for (int mt = 0; mt < 2; ++mt) {
                const int row = Rb + mt * 16 + (li & 1) * 8 + lr;
                const int col = k0g + (li >> 1) * 8;
                const uint32_t off = (uint32_t)(row * AS + col) * 2;
                ldsm4(Ahf[mt], uAh + off);
                ldsm4(Alf[mt], uAl + off);
            }
            uint32_t Bhf[2][4], Blf[2][4];
            #pragma unroll
            for (int nt = 0; nt < 2; ++nt) {
                const int n  = Nb + nt * 16 + (li >> 1) * 8 + lr;
                const int kk = kloc + (li & 1) * 8;
                const uint32_t off = (uint32_t)(n * BS + kk) * 2;
                ldsm4(Bhf[nt], bufb + off);
                ldsm4(Blf[nt], bufb + (uint32_t)(128 * BS * 2) + off);
            }
            #pragma unroll
            for (int mt = 0; mt < 2; ++mt)
                #pragma unroll
                for (int nt = 0; nt < 2; ++nt)
                    #pragma unroll
                    for (int h = 0; h < 2; ++h) {
                        float* c = acc[mt][nt * 2 + h];
                        mma_bf16(c, Ahf[mt], Bhf[nt][2 * h], Bhf[nt][2 * h + 1]);
                        mma_bf16(c, Ahf[mt], Blf[nt][2 * h], Blf[nt][2 * h + 1]);
                        mma_bf16(c, Alf[mt], Bhf[nt][2 * h], Bhf[nt][2 * h + 1]);
                    }
        }

        if (kc + 2 < 8) {
            __syncthreads();       // all warps done reading buf kc&1
            load_chunk(kc + 2, kc & 1);
        }
    }

    // ---------------- epilogue: bias + relu + row l2-norm + store ----------
    const int rg = lane >> 2;          // 0..7 row within 8-row group
    const int lc = (lane & 3) * 2;     // 2-col pair base

    float bb[4][2];
    #pragma unroll
    for (int nt = 0; nt < 4; ++nt) {
        bb[nt][0] = S.bias[Nb + nt * 8 + lc];
        bb[nt][1] = S.bias[Nb + nt * 8 + lc + 1];
    }

    #pragma unroll
    for (int mt = 0; mt < 2; ++mt)
        #pragma unroll
        for (int rh = 0; rh < 2; ++rh) {
            float ss = 0.f;
            #pragma unroll
            for (int nt = 0; nt < 4; ++nt) {
                float v0 = fmaxf(acc[mt][nt][2 * rh]     + bb[nt][0], 0.f);
                float v1 = fmaxf(acc[mt][nt][2 * rh + 1] + bb[nt][1], 0.f);
                acc[mt][nt][2 * rh]     = v0;
                acc[mt][nt][2 * rh + 1] = v1;
                ss += v0 * v0 + v1 * v1;
            }
            ss += __shfl_xor_sync(0xffffffffu, ss, 1);
            ss += __shfl_xor_sync(0xffffffffu, ss, 2);
            if ((lane & 3) == 0)
                S.red[wn][Rb + mt * 16 + rh * 8 + rg] = ss;
        }
    __syncthreads();

    if (tid < BM) {
        const float t = S.red[0][tid] + S.red[1][tid] + S.red[2][tid] + S.red[3][tid];
        S.inv[tid] = 1.0f / fmaxf(sqrtf(t), 1e-12f);
    }
    __syncthreads();

    #pragma unroll
    for (int mt = 0; mt < 2; ++mt)
        #pragma unroll
        for (int rh = 0; rh < 2; ++rh) {
            const int row = Rb + mt * 16 + rh * 8 + rg;
            const float inv = S.inv[row];
            float* orow = out + (size_t)(m0 + row) * 128 + Nb + lc;
            #pragma unroll
            for (int nt = 0; nt < 4; ++nt)
                *(float2*)(orow + nt * 8) =
                    make_float2(acc[mt][nt][2 * rh] * inv,
                                acc[mt][nt][2 * rh + 1] * inv);
        }
}

extern "C" void kernel_launch(void* const* d_in, const int* in_sizes, int n_in,
                              void* d_out, int out_size)
{
    (void)in_sizes; (void)n_in; (void)out_size;

    const float* features = (const float*)d_in[0];
    const float* W0       = (const float*)d_in[1];
    const float* b0       = (const float*)d_in[2];
    const float* W1       = (const float*)d_in[3];
    const float* b1       = (const float*)d_in[4];
    const int*   nodes    = (const int*)d_in[5];
    const int*   nbr1     = (const int*)d_in[6];
    const int*   nbr0     = (const int*)d_in[7];
    float*       out      = (float*)d_out;

    const int SMEM = (int)sizeof(Smem);   // 110336 B -> occupancy 2

    cudaFuncSetAttribute(sage_hmma<0>,
                         cudaFuncAttributeMaxDynamicSharedMemorySize, SMEM);
    cudaFuncSetAttribute(sage_hmma<0>,
                         cudaFuncAttributePreferredSharedMemoryCarveout, 100);
    cudaFuncSetAttribute(sage_hmma<1>,
                         cudaFuncAttributeMaxDynamicSharedMemorySize, SMEM);
    cudaFuncSetAttribute(sage_hmma<1>,
                         cudaFuncAttributePreferredSharedMemoryCarveout, 100);

    float *h1; __nv_bfloat16 *w0h, *w0l, *w1h, *w1l;
    cudaGetSymbolAddress((void**)&h1,  g_h1);
    cudaGetSymbolAddress((void**)&w0h, g_W0h);
    cudaGetSymbolAddress((void**)&w0l, g_W0l);
    cudaGetSymbolAddress((void**)&w1h, g_W1h);
    cudaGetSymbolAddress((void**)&w1l, g_W1l);

    prep_w<<<128, 256>>>(W0, W1);
    sage_hmma<0><<<L1_ROWS / BM, THREADS, SMEM>>>(
        features, nodes, nbr1, nbr0, w0h, w0l, b0, h1);
    sage_hmma<1><<<B_TARGETS / BM, THREADS, SMEM>>>(
        h1, nullptr, nullptr, nullptr, w1h, w1l, b1, out);
}

// round 11
// speedup vs baseline: 1.2468x; 1.0395x over previous
#include <cuda_runtime.h>
#include <cuda_bf16.h>
#include <cstdint>
#include <cstddef>

#define THREADS   256
#define BM        32
#define AS        264    // A row stride (bf16): 528B rows, ldmatrix conflict-free
#define BS        40     // B row stride (bf16): 80B rows, conflict-free
#define B_TARGETS 4096
#define L1_ROWS   (B_TARGETS * 11)   // 45056

__device__ __align__(256) float         g_h1[L1_ROWS * 128];
__device__ __align__(256) __nv_bfloat16 g_W0h[128 * 256];
__device__ __align__(256) __nv_bfloat16 g_W0l[128 * 256];
__device__ __align__(256) __nv_bfloat16 g_W1h[128 * 256];
__device__ __align__(256) __nv_bfloat16 g_W1l[128 * 256];

typedef unsigned long long u64;

__device__ __forceinline__ float bfrt(float x) {
    float r;
    asm("{\n\t.reg .b16 t;\n\tcvt.rn.bf16.f32 t, %1;\n\tcvt.f32.bf16 %0, t;\n\t}"
        : "=f"(r) : "f"(x));
    return r;
}
__device__ __forceinline__ uint32_t pk_bf16(float x, float y) {
    uint32_t r;
    asm("{\n\t.reg .b16 l, h;\n\tcvt.rn.bf16.f32 l, %1;\n\tcvt.rn.bf16.f32 h, %2;\n\t"
        "mov.b32 %0, {l, h};\n\t}" : "=r"(r) : "f"(x), "f"(y));
    return r;
}
__device__ __forceinline__ void add2(u64& d, u64 a) {
    asm("add.rn.f32x2 %0, %1, %0;" : "+l"(d) : "l"(a));
}
__device__ __forceinline__ u64 pack2(float lo, float hi) {
    u64 r; asm("mov.b64 %0, {%1, %2};" : "=l"(r) : "f"(lo), "f"(hi)); return r;
}
__device__ __forceinline__ float2 unpack2(u64 v) {
    float2 r; asm("mov.b64 {%0, %1}, %2;" : "=f"(r.x), "=f"(r.y) : "l"(v)); return r;
}
__device__ __forceinline__ u64 mul2(u64 a, u64 b) {
    u64 r; asm("mul.rn.f32x2 %0, %1, %2;" : "=l"(r) : "l"(a), "l"(b)); return r;
}
__device__ __forceinline__ void cpa8(uint32_t dst, const void* src) {
    asm volatile("cp.async.ca.shared.global [%0], [%1], 8;" :: "r"(dst), "l"(src));
}
__device__ __forceinline__ void cpa_commit() {
    asm volatile("cp.async.commit_group;");
}
template <int N>
__device__ __forceinline__ void cpa_wait() {
    asm volatile("cp.async.wait_group %0;" :: "n"(N));
}
__device__ __forceinline__ void ldsm4(uint32_t* r, uint32_t addr) {
    asm volatile("ldmatrix.sync.aligned.m8n8.x4.shared.b16 {%0,%1,%2,%3}, [%4];"
                 : "=r"(r[0]), "=r"(r[1]), "=r"(r[2]), "=r"(r[3]) : "r"(addr));
}
__device__ __forceinline__ void mma_bf16(float* c, const uint32_t* a,
                                         uint32_t b0, uint32_t b1) {
    asm volatile("mma.sync.aligned.m16n8k16.row.col.f32.bf16.bf16.f32 "
                 "{%0,%1,%2,%3}, {%4,%5,%6,%7}, {%8,%9}, {%0,%1,%2,%3};"
                 : "+f"(c[0]), "+f"(c[1]), "+f"(c[2]), "+f"(c[3])
                 : "r"(a[0]), "r"(a[1]), "r"(a[2]), "r"(a[3]), "r"(b0), "r"(b1));
}

__global__ void prep_w(const float* __restrict__ W0, const float* __restrict__ W1) {
    const int i = blockIdx.x * 256 + threadIdx.x;      // 0..32767
    const float a = W0[i], b = W1[i];
    g_W0h[i] = __float2bfloat16(a);
    g_W0l[i] = __float2bfloat16(a - bfrt(a));
    g_W1h[i] = __float2bfloat16(b);
    g_W1l[i] = __float2bfloat16(b - bfrt(b));
}

// Fused tile: register-LDG gather (paired rows, 2x MLP) -> bf16 hi/lo A ->
// HMMA (3-product bf16 split, fp32 accum) -> bias+relu+row-l2norm -> out.
// BM=32 rows/block; 8 warps each own 16 output cols (Nb=warp*16) over all rows.
// LAYER 0: rows = level-1 nodes (self feat || mean of 25 nbr feats).
// LAYER 1: rows = targets       (h1[b,0]   || mean of h1[b,1..10]).
template <int LAYER>
__global__ __launch_bounds__(THREADS, 3)
void sage_hmma(const float* __restrict__ src,
               const int*   __restrict__ nodes,
               const int*   __restrict__ nbr1,
               const int*   __restrict__ nbr0,
               const __nv_bfloat16* __restrict__ Wh,   // [128 n][256 k]
               const __nv_bfloat16* __restrict__ Wl,
               const float* __restrict__ bias,
               float*       __restrict__ out)          // [rows][128]
{
    extern __shared__ char sm[];
    __nv_bfloat16* Ah  = (__nv_bfloat16*)sm;           // BM*AS
    __nv_bfloat16* Al  = Ah + BM * AS;                 // BM*AS
    __nv_bfloat16* Bsm = Al + BM * AS;                 // [2 hl][128][BS]
    float* sBias = (float*)(Bsm + 2 * 128 * BS);       // 128
    float* red   = sBias + 128;                        // [8][BM]
    float* sInv  = red + 8 * BM;                       // BM

    const int tid  = threadIdx.x;
    const int warp = tid >> 5;
    const int lane = tid & 31;
    const int m0   = blockIdx.x * BM;
    const int Nb   = warp * 16;

    const uint32_t uAh = (uint32_t)__cvta_generic_to_shared(Ah);
    const uint32_t uAl = (uint32_t)__cvta_generic_to_shared(Al);
    const uint32_t uB  = (uint32_t)__cvta_generic_to_shared(Bsm);

    // B chunk 0 (32 k-cols, hi+lo) via cp.async — lands during the gather.
    {
        #pragma unroll
        for (int t = 0; t < 8; ++t) {
            const int e  = tid + t * THREADS;   // 0..2047
            const int hl = e >> 10;
            const int n  = (e >> 3) & 127;
            const int pc = e & 7;               // 8B piece within 32 cols
            cpa8(uB + (uint32_t)(hl * 128 * BS + n * BS + pc * 4) * 2,
                 (hl ? Wl : Wh) + n * 256 + pc * 4);
        }
        cpa_commit();
    }

    if (tid < 128) sBias[tid] = bias[tid];

    // ---------------- gather: warp w builds rows w*4 .. w*4+3, in pairs ----
    auto storeA = [&](int mL, float4 s4, float2 m01, float2 m23) {
        __nv_bfloat16* rowH = Ah + mL * AS;
        __nv_bfloat16* rowL = Al + mL * AS;
        *(uint2*)(rowH + 4 * lane) =
            make_uint2(pk_bf16(s4.x, s4.y), pk_bf16(s4.z, s4.w));
        *(uint2*)(rowL + 4 * lane) =
            make_uint2(pk_bf16(s4.x - bfrt(s4.x), s4.y - bfrt(s4.y)),
                       pk_bf16(s4.z - bfrt(s4.z), s4.w - bfrt(s4.w)));
        *(uint2*)(rowH + 128 + 4 * lane) =
            make_uint2(pk_bf16(m01.x, m01.y), pk_bf16(m23.x, m23.y));
        *(uint2*)(rowL + 128 + 4 * lane) =
            make_uint2(pk_bf16(m01.x - bfrt(m01.x), m01.y - bfrt(m01.y)),
                       pk_bf16(m23.x - bfrt(m23.x), m23.y - bfrt(m23.y)));
    };

    #pragma unroll 1
    for (int r0 = 0; r0 < 4; r0 += 2) {
        const int mLa = warp * 4 + r0;
        const int mLb = mLa + 1;
        float4 selfA, selfB;
        u64 pa01 = 0, pa23 = 0, qa01 = 0, qa23 = 0;   // row-a chains
        u64 pb01 = 0, pb23 = 0, qb01 = 0, qb23 = 0;   // row-b chains
        u64 scale;

        if (LAYER == 0) {
            const int jA = m0 + mLa, bA = jA / 11, cA = jA - bA * 11;
            const int jB = m0 + mLb, bB = jB / 11, cB = jB - bB * 11;
            const int sA = (cA == 0) ? __ldg(&nodes[bA])
                                     : __ldg(&nbr1[bA * 10 + cA - 1]);
            const int sB = (cB == 0) ? __ldg(&nodes[bB])
                                     : __ldg(&nbr1[bB * 10 + cB - 1]);
            int idxA = (lane < 25) ? __ldg(&nbr0[(size_t)jA * 25 + lane]) : 0;
            int idxB = (lane < 25) ? __ldg(&nbr0[(size_t)jB * 25 + lane]) : 0;
            selfA = ((const float4*)(src + (size_t)sA * 128))[lane];
            selfB = ((const float4*)(src + (size_t)sB * 128))[lane];
            #pragma unroll
            for (int s = 0; s < 25; ++s) {
                const int na = __shfl_sync(0xffffffffu, idxA, s);
                const int nb = __shfl_sync(0xffffffffu, idxB, s);
                float4 va = ((const float4*)(src + (size_t)na * 128))[lane];
                float4 vb = ((const float4*)(src + (size_t)nb * 128))[lane];
                if (s & 1) {
                    add2(qa01, pack2(va.x, va.y)); add2(qa23, pack2(va.z, va.w));
                    add2(qb01, pack2(vb.x, vb.y)); add2(qb23, pack2(vb.z, vb.w));
                } else {
                    add2(pa01, pack2(va.x, va.y)); add2(pa23, pack2(va.z, va.w));
                    add2(pb01, pack2(vb.x, vb.y)); add2(pb23, pack2(vb.z, vb.w));
                }
            }
            scale = pack2(1.0f / 25.0f, 1.0f / 25.0f);
        } else {
            const float* baseA = src + (size_t)(m0 + mLa) * (11 * 128);
            const float* baseB = src + (size_t)(m0 + mLb) * (11 * 128);
            selfA = ((const float4*)baseA)[lane];
            selfB = ((const float4*)baseB)[lane];
            #pragma unroll
            for (int s = 1; s <= 10; ++s) {
                float4 va = ((const float4*)(baseA + s * 128))[lane];
                float4 vb = ((const float4*)(baseB + s * 128))[lane];
                if (s & 1) {
                    add2(qa01, pack2(va.x, va.y)); add2(qa23, pack2(va.z, va.w));
                    add2(qb01, pack2(vb.x, vb.y)); add2(qb23, pack2(vb.z, vb.w));
                } else {
                    add2(pa01, pack2(va.x, va.y)); add2(pa23, pack2(va.z, va.w));
                    add2(pb01, pack2(vb.x, vb.y)); add2(pb23, pack2(vb.z, vb.w));
                }
            }
            scale = pack2(0.1f, 0.1f);
        }

        add2(pa01, qa01); add2(pa23, qa23);
        add2(pb01, qb01); add2(pb23, qb23);
        storeA(mLa, selfA, unpack2(mul2(pa01, scale)), unpack2(mul2(pa23, scale)));
        storeA(mLb, selfB, unpack2(mul2(pb01, scale)), unpack2(mul2(pb23, scale)));
    }

    cpa_wait<0>();
    __syncthreads();                 // A tile + B chunk 0 published

    // ---------------- HMMA mainloop: single B buffer + reg prefetch --------
    float acc[2][2][4];              // [mt 16-row][8-col group][frag]
    #pragma unroll
    for (int mt = 0; mt < 2; ++mt)
        #pragma unroll
        for (int g = 0; g < 2; ++g)
            #pragma unroll
            for (int c = 0; c < 4; ++c) acc[mt][g][c] = 0.f;

    const int li = lane >> 3, lr = lane & 7;
    int4 stg4[4];

    #pragma unroll 1
    for (int kc = 0; kc < 8; ++kc) {
        if (kc < 7) {                // prefetch next chunk into regs (hi, lo)
            #pragma unroll
            for (int t = 0; t < 2; ++t) {
                const int e = tid + t * THREADS;  // 0..511
                const int n = e >> 2, pc = e & 3;
                stg4[t]     = *(const int4*)(Wh + n * 256 + (kc + 1) * 32 + pc * 8);
                stg4[2 + t] = *(const int4*)(Wl + n * 256 + (kc + 1) * 32 + pc * 8);
            }
        }
        #pragma unroll
        for (int s = 0; s < 2; ++s) {
            const int k0g = kc * 32 + s * 16;
            uint32_t Ahf[2][4], Alf[2][4];
            #pragma unroll
            for (int mt = 0; mt < 2; ++mt) {
                const int row = mt * 16 + (li & 1) * 8 + lr;
                const int col = k0g + (li >> 1) * 8;
                const uint32_t off = (uint32_t)(row * AS + col) * 2;
                ldsm4(Ahf[mt], uAh + off);
                ldsm4(Alf[mt], uAl + off);
            }
            uint32_t Bhf[4], Blf[4];
            {
                const int n  = Nb + (li >> 1) * 8 + lr;
                const int kk = s * 16 + (li & 1) * 8;
                const uint32_t off = (uint32_t)(n * BS + kk) * 2;
                ldsm4(Bhf, uB + off);
                ldsm4(Blf, uB + (uint32_t)(128 * BS * 2) + off);
            }
            #pragma unroll
            for (int mt = 0; mt < 2; ++mt)
                #pragma unroll
                for (int h = 0; h < 2; ++h) {
                    float* c = acc[mt][h];
                    mma_bf16(c, Ahf[mt], Bhf[2 * h], Bhf[2 * h + 1]);
                    mma_bf16(c, Ahf[mt], Blf[2 * h], Blf[2 * h + 1]);
                    mma_bf16(c, Alf[mt], Bhf[2 * h], Bhf[2 * h + 1]);
                }
        }
        if (kc < 7) {
            __syncthreads();         // all warps done reading B chunk kc
            #pragma unroll
            for (int t = 0; t < 2; ++t) {
                const int e = tid + t * THREADS;
                const int n = e >> 2, pc = e & 3;
                *(int4*)(Bsm + n * BS + pc * 8)            = stg4[t];
                *(int4*)(Bsm + 128 * BS + n * BS + pc * 8) = stg4[2 + t];
            }
            __syncthreads();         // chunk kc+1 published
        }
    }

    // ---------------- epilogue: bias + relu + row l2-norm + store ----------
    const int rg = lane >> 2;
    const int lc = (lane & 3) * 2;

    float bb[2][2];
    #pragma unroll
    for (int g = 0; g < 2; ++g) {
        bb[g][0] = sBias[Nb + g * 8 + lc];
        bb[g][1] = sBias[Nb + g * 8 + lc + 1];
    }

    #pragma unroll
    for (int mt = 0; mt < 2; ++mt)
        #pragma unroll
        for (int rh = 0; rh < 2; ++rh) {
            float ss = 0.f;
            #pragma unroll
            for (int g = 0; g < 2; ++g) {
                float v0 = fmaxf(acc[mt][g][2 * rh]     + bb[g][0], 0.f);
                float v1 = fmaxf(acc[mt][g][2 * rh + 1] + bb[g][1], 0.f);
                acc[mt][g][2 * rh]     = v0;
                acc[mt][g][2 * rh + 1] = v1;
                ss += v0 * v0 + v1 * v1;
            }
            ss += __shfl_xor_sync(0xffffffffu, ss, 1);
            ss += __shfl_xor_sync(0xffffffffu, ss, 2);
            if ((lane & 3) == 0)
                red[warp * BM + mt * 16 + rh * 8 + rg] = ss;
        }
    __syncthreads();

    if (tid < BM) {
        float t = 0.f;
        #pragma unroll
        for (int n = 0; n < 8; ++n) t += red[n * BM + tid];
        sInv[tid] = 1.0f / fmaxf(sqrtf(t), 1e-12f);
    }
    __syncthreads();

    #pragma unroll
    for (int mt = 0; mt < 2; ++mt)
        #pragma unroll
        for (int rh = 0; rh < 2; ++rh) {
            const int row = mt * 16 + rh * 8 + rg;
            const float inv = sInv[row];
            float* orow = out + (size_t)(m0 + row) * 128 + Nb + lc;
            #pragma unroll
            for (int g = 0; g < 2; ++g)
                *(float2*)(orow + g * 8) =
                    make_float2(acc[mt][g][2 * rh] * inv,
                                acc[mt][g][2 * rh + 1] * inv);
        }
}

extern "C" void kernel_launch(void* const* d_in, const int* in_sizes, int n_in,
                              void* d_out, int out_size)
{
    (void)in_sizes; (void)n_in; (void)out_size;

    const float* features = (const float*)d_in[0];
    const float* W0       = (const float*)d_in[1];
    const float* b0       = (const float*)d_in[2];
    const float* W1       = (const float*)d_in[3];
    const float* b1       = (const float*)d_in[4];
    const int*   nodes    = (const int*)d_in[5];
    const int*   nbr1     = (const int*)d_in[6];
    const int*   nbr0     = (const int*)d_in[7];
    float*       out      = (float*)d_out;

    // smem: 2*32*264*2 + 2*128*40*2 + 512 + 8*32*4 + 32*4 = 55936 B -> occ 3
    const int SMEM = 2 * BM * AS * 2 + 2 * 128 * BS * 2 + 512
                     + 8 * BM * 4 + BM * 4;

    cudaFuncSetAttribute(sage_hmma<0>,
                         cudaFuncAttributeMaxDynamicSharedMemorySize, SMEM);
    cudaFuncSetAttribute(sage_hmma<0>,
                         cudaFuncAttributePreferredSharedMemoryCarveout, 100);
    cudaFuncSetAttribute(sage_hmma<1>,
                         cudaFuncAttributeMaxDynamicSharedMemorySize, SMEM);
    cudaFuncSetAttribute(sage_hmma<1>,
                         cudaFuncAttributePreferredSharedMemoryCarveout, 100);

    float *h1; __nv_bfloat16 *w0h, *w0l, *w1h, *w1l;
    cudaGetSymbolAddress((void**)&h1,  g_h1);
    cudaGetSymbolAddress((void**)&w0h, g_W0h);
    cudaGetSymbolAddress((void**)&w0l, g_W0l);
    cudaGetSymbolAddress((void**)&w1h, g_W1h);
    cudaGetSymbolAddress((void**)&w1l, g_W1l);

    prep_w<<<128, 256>>>(W0, W1);
    sage_hmma<0><<<L1_ROWS / BM, THREADS, SMEM>>>(
        features, nodes, nbr1, nbr0, w0h, w0l, b0, h1);
    sage_hmma<1><<<B_TARGETS / BM, THREADS, SMEM>>>(
        h1, nullptr, nullptr, nullptr, w1h, w1l, b1, out);
}